// round 14
// baseline (speedup 1.0000x reference)
#include <cuda_runtime.h>
#include <cuda_bf16.h>

#define ALPHA_MARGIN 1.0f

// FINAL STRUCTURE (reproduced 4x at the top: 80.38us R2/R12/R13, 80.64us R10).
// Persistent grid-stride: each warp processes 2 pairs per iteration
// (4 x LDG.128 per lane, fully coalesced 512B chunks), next iteration
// prefetched before the current reduction (~8 LDG.128 in flight).
// HBM-streaming-bound at the chip's ~6.9TB/s ceiling (87% DRAM measured).
// This round's only delta: grid 2048 -> 4096 (finer tail granularity).
__global__ __launch_bounds__(256) void contrastive_loss_kernel(
    const float* __restrict__ X,
    const int*   __restrict__ y,
    float*       __restrict__ out,
    int n_pairs)
{
    const int lane   = threadIdx.x & 31;
    const int gwarp  = (blockIdx.x * blockDim.x + threadIdx.x) >> 5;
    const int nwarps = (gridDim.x * blockDim.x) >> 5;
    const int stride = nwarps * 2;

    const float4* Xv = reinterpret_cast<const float4*>(X);
    int p = gwarp * 2;

    float4 a0, b0, a1, b1;
    if (p < n_pairs) {
        const float4* r0 = Xv + (size_t)p * 64;
        a0 = __ldg(r0 + lane);
        b0 = __ldg(r0 + 32 + lane);
    }
    if (p + 1 < n_pairs) {
        const float4* r1 = Xv + (size_t)(p + 1) * 64;
        a1 = __ldg(r1 + lane);
        b1 = __ldg(r1 + 32 + lane);
    }

    while (p < n_pairs) {
        const int pn = p + stride;

        // Prefetch next iteration before reducing current
        float4 na0, nb0, na1, nb1;
        if (pn < n_pairs) {
            const float4* r0 = Xv + (size_t)pn * 64;
            na0 = __ldg(r0 + lane);
            nb0 = __ldg(r0 + 32 + lane);
        }
        if (pn + 1 < n_pairs) {
            const float4* r1 = Xv + (size_t)(pn + 1) * 64;
            na1 = __ldg(r1 + lane);
            nb1 = __ldg(r1 + 32 + lane);
        }

        // Pair p
        {
            float dx = a0.x - b0.x, dy = a0.y - b0.y;
            float dz = a0.z - b0.z, dw = a0.w - b0.w;
            float s = dx * dx + dy * dy + dz * dz + dw * dw;
            #pragma unroll
            for (int o = 16; o > 0; o >>= 1)
                s += __shfl_xor_sync(0xffffffffu, s, o);
            if (lane == 0) {
                int adj = y[p];
                out[p] = (adj == 1) ? s
                       : (adj == 0) ? fmaxf(ALPHA_MARGIN - s, 0.0f)
                       : 0.0f;
            }
        }

        // Pair p+1
        if (p + 1 < n_pairs) {
            float dx = a1.x - b1.x, dy = a1.y - b1.y;
            float dz = a1.z - b1.z, dw = a1.w - b1.w;
            float s = dx * dx + dy * dy + dz * dz + dw * dw;
            #pragma unroll
            for (int o = 16; o > 0; o >>= 1)
                s += __shfl_xor_sync(0xffffffffu, s, o);
            if (lane == 0) {
                int adj = y[p + 1];
                out[p + 1] = (adj == 1) ? s
                           : (adj == 0) ? fmaxf(ALPHA_MARGIN - s, 0.0f)
                           : 0.0f;
            }
        }

        a0 = na0; b0 = nb0; a1 = na1; b1 = nb1;
        p = pn;
    }
}

extern "C" void kernel_launch(void* const* d_in, const int* in_sizes, int n_in,
                              void* d_out, int out_size)
{
    const float* X = (const float*)d_in[0];
    const int*   y = (const int*)d_in[1];
    float*       out = (float*)d_out;

    int n_pairs = out_size;      // B*N*N = 524288
    int blocks  = 4096;          // only delta vs locked config (was 2048)
    contrastive_loss_kernel<<<blocks, 256>>>(X, y, out, n_pairs);
}

// round 15
// speedup vs baseline: 1.0199x; 1.0199x over previous
#include <cuda_runtime.h>
#include <cuda_bf16.h>

#define ALPHA_MARGIN 1.0f

// FINAL KERNEL — best configuration, reproduced four times at the top
// (80.38us R2/R12/R13, 80.64us R10). Persistent grid-stride: each warp
// processes 2 pairs per iteration (4 x LDG.128 per lane, fully coalesced
// 512B chunks), with the next iteration's loads prefetched before the
// current reduction so ~8 LDG.128 stay in flight through the SHFL chain.
//
// HBM-streaming-bound: 541MB compulsory traffic / ~6.9TB/s effective chip
// ceiling = ~79us floor; this kernel measures ~98% of it (87.2% DRAM best
// snapshot). Exhaustively tested and rejected: PAIRS={1,4}, grid={740,4096,
// 65536}, .cs hints, label prefetch (x2), fused float2 store, exact-division
// unguarded loop, merged 4-way reduction, redux.sync.f32 (not on sm_103).
__global__ __launch_bounds__(256) void contrastive_loss_kernel(
    const float* __restrict__ X,
    const int*   __restrict__ y,
    float*       __restrict__ out,
    int n_pairs)
{
    const int lane   = threadIdx.x & 31;
    const int gwarp  = (blockIdx.x * blockDim.x + threadIdx.x) >> 5;
    const int nwarps = (gridDim.x * blockDim.x) >> 5;
    const int stride = nwarps * 2;

    const float4* Xv = reinterpret_cast<const float4*>(X);
    int p = gwarp * 2;

    float4 a0, b0, a1, b1;
    if (p < n_pairs) {
        const float4* r0 = Xv + (size_t)p * 64;
        a0 = __ldg(r0 + lane);
        b0 = __ldg(r0 + 32 + lane);
    }
    if (p + 1 < n_pairs) {
        const float4* r1 = Xv + (size_t)(p + 1) * 64;
        a1 = __ldg(r1 + lane);
        b1 = __ldg(r1 + 32 + lane);
    }

    while (p < n_pairs) {
        const int pn = p + stride;

        // Prefetch next iteration before reducing current
        float4 na0, nb0, na1, nb1;
        if (pn < n_pairs) {
            const float4* r0 = Xv + (size_t)pn * 64;
            na0 = __ldg(r0 + lane);
            nb0 = __ldg(r0 + 32 + lane);
        }
        if (pn + 1 < n_pairs) {
            const float4* r1 = Xv + (size_t)(pn + 1) * 64;
            na1 = __ldg(r1 + lane);
            nb1 = __ldg(r1 + 32 + lane);
        }

        // Pair p
        {
            float dx = a0.x - b0.x, dy = a0.y - b0.y;
            float dz = a0.z - b0.z, dw = a0.w - b0.w;
            float s = dx * dx + dy * dy + dz * dz + dw * dw;
            #pragma unroll
            for (int o = 16; o > 0; o >>= 1)
                s += __shfl_xor_sync(0xffffffffu, s, o);
            if (lane == 0) {
                int adj = y[p];
                out[p] = (adj == 1) ? s
                       : (adj == 0) ? fmaxf(ALPHA_MARGIN - s, 0.0f)
                       : 0.0f;
            }
        }

        // Pair p+1
        if (p + 1 < n_pairs) {
            float dx = a1.x - b1.x, dy = a1.y - b1.y;
            float dz = a1.z - b1.z, dw = a1.w - b1.w;
            float s = dx * dx + dy * dy + dz * dz + dw * dw;
            #pragma unroll
            for (int o = 16; o > 0; o >>= 1)
                s += __shfl_xor_sync(0xffffffffu, s, o);
            if (lane == 0) {
                int adj = y[p + 1];
                out[p + 1] = (adj == 1) ? s
                           : (adj == 0) ? fmaxf(ALPHA_MARGIN - s, 0.0f)
                           : 0.0f;
            }
        }

        a0 = na0; b0 = nb0; a1 = na1; b1 = nb1;
        p = pn;
    }
}

extern "C" void kernel_launch(void* const* d_in, const int* in_sizes, int n_in,
                              void* d_out, int out_size)
{
    const float* X = (const float*)d_in[0];
    const int*   y = (const int*)d_in[1];
    float*       out = (float*)d_out;

    int n_pairs = out_size;      // B*N*N = 524288
    int blocks  = 2048;          // best-measured shape (4x reproduced)
    contrastive_loss_kernel<<<blocks, 256>>>(X, y, out, n_pairs);
}

// round 16
// speedup vs baseline: 1.0232x; 1.0032x over previous
#include <cuda_runtime.h>
#include <cuda_bf16.h>

#define ALPHA_MARGIN 1.0f

// FINAL KERNEL — locked. Reproduced five times at the top of the table:
// 80.352us (R15), 80.384us (R2/R12/R13), 80.640us (R10).
//
// Persistent grid-stride: each warp processes 2 pairs per iteration
// (4 x LDG.128 per lane, fully coalesced 512B chunks), with the next
// iteration's loads prefetched before the current reduction so ~8 LDG.128
// stay in flight through the SHFL chain.
//
// HBM-streaming-bound: 541MB compulsory traffic / ~6.9TB/s effective chip
// ceiling = ~78.7us floor; this kernel measures ~98% of it. Exhaustively
// tested and rejected over 14 rounds: PAIRS={1,4}, grid={740,4096,65536},
// .cs hints, label prefetch (x2 variants), fused float2 store, exact-division
// unguarded loop, merged 4-way shuffle reduction, redux.sync.f32 (unsupported
// on sm_103). Bandwidth is invariant (6.6-6.9 TB/s) across all of them — the
// chip's streaming ceiling, not a kernel limitation.
__global__ __launch_bounds__(256) void contrastive_loss_kernel(
    const float* __restrict__ X,
    const int*   __restrict__ y,
    float*       __restrict__ out,
    int n_pairs)
{
    const int lane   = threadIdx.x & 31;
    const int gwarp  = (blockIdx.x * blockDim.x + threadIdx.x) >> 5;
    const int nwarps = (gridDim.x * blockDim.x) >> 5;
    const int stride = nwarps * 2;

    const float4* Xv = reinterpret_cast<const float4*>(X);
    int p = gwarp * 2;

    float4 a0, b0, a1, b1;
    if (p < n_pairs) {
        const float4* r0 = Xv + (size_t)p * 64;
        a0 = __ldg(r0 + lane);
        b0 = __ldg(r0 + 32 + lane);
    }
    if (p + 1 < n_pairs) {
        const float4* r1 = Xv + (size_t)(p + 1) * 64;
        a1 = __ldg(r1 + lane);
        b1 = __ldg(r1 + 32 + lane);
    }

    while (p < n_pairs) {
        const int pn = p + stride;

        // Prefetch next iteration before reducing current
        float4 na0, nb0, na1, nb1;
        if (pn < n_pairs) {
            const float4* r0 = Xv + (size_t)pn * 64;
            na0 = __ldg(r0 + lane);
            nb0 = __ldg(r0 + 32 + lane);
        }
        if (pn + 1 < n_pairs) {
            const float4* r1 = Xv + (size_t)(pn + 1) * 64;
            na1 = __ldg(r1 + lane);
            nb1 = __ldg(r1 + 32 + lane);
        }

        // Pair p
        {
            float dx = a0.x - b0.x, dy = a0.y - b0.y;
            float dz = a0.z - b0.z, dw = a0.w - b0.w;
            float s = dx * dx + dy * dy + dz * dz + dw * dw;
            #pragma unroll
            for (int o = 16; o > 0; o >>= 1)
                s += __shfl_xor_sync(0xffffffffu, s, o);
            if (lane == 0) {
                int adj = y[p];
                out[p] = (adj == 1) ? s
                       : (adj == 0) ? fmaxf(ALPHA_MARGIN - s, 0.0f)
                       : 0.0f;
            }
        }

        // Pair p+1
        if (p + 1 < n_pairs) {
            float dx = a1.x - b1.x, dy = a1.y - b1.y;
            float dz = a1.z - b1.z, dw = a1.w - b1.w;
            float s = dx * dx + dy * dy + dz * dz + dw * dw;
            #pragma unroll
            for (int o = 16; o > 0; o >>= 1)
                s += __shfl_xor_sync(0xffffffffu, s, o);
            if (lane == 0) {
                int adj = y[p + 1];
                out[p + 1] = (adj == 1) ? s
                           : (adj == 0) ? fmaxf(ALPHA_MARGIN - s, 0.0f)
                           : 0.0f;
            }
        }

        a0 = na0; b0 = nb0; a1 = na1; b1 = nb1;
        p = pn;
    }
}

extern "C" void kernel_launch(void* const* d_in, const int* in_sizes, int n_in,
                              void* d_out, int out_size)
{
    const float* X = (const float*)d_in[0];
    const int*   y = (const int*)d_in[1];
    float*       out = (float*)d_out;

    int n_pairs = out_size;      // B*N*N = 524288
    int blocks  = 2048;          // best-measured shape (5x reproduced)
    contrastive_loss_kernel<<<blocks, 256>>>(X, y, out, n_pairs);
}